// round 16
// baseline (speedup 1.0000x reference)
#include <cuda_runtime.h>
#include <cuda_bf16.h>
#include <stdint.h>

#define NN 50000
#define EE 800000
#define TT 8
#define NB_SCAN 196

__device__ int   g_is64_adj, g_is64_et, g_is64_nt;
__device__ int   g_ticket1, g_ticket2;
__device__ float g_knode[(size_t)NN*64];
__device__ float g_vnode[(size_t)NN*64];
__device__ __nv_bfloat16 g_qnH[(size_t)NN*64], g_qnL[(size_t)NN*64];
__device__ __nv_bfloat16 g_wTH[3*TT*4096], g_wTL[3*TT*4096];
__device__ __nv_bfloat16 g_attH[512*64], g_attL[512*64];   // pri[r]/8 folded in
__device__ __nv_bfloat16 g_msgTH[64*512], g_msgTL[64*512];
__device__ float g_qrel[(size_t)NN*512];
__device__ __nv_bfloat16 g_bkH[(size_t)NN*512], g_bkL[(size_t)NN*512];
__device__ float g_aggM[(size_t)NN*64];
__device__ int g_perm[NN], g_iperm[NN], g_deg[NN], g_cursor[NN], g_rowptr[NN+1];
__device__ int g_bsum[256], g_boff[256], g_tcount[TT], g_tbase[TT], g_tcur[TT];
__device__ int g_csr[EE];

__device__ __forceinline__ int ld_idx(const void* p, long i, int is64) {
    if (is64) return (int)(((const long long*)p)[i]);
    return ((const int*)p)[i];
}
__device__ __forceinline__ void mma_bf16(float* d, const uint32_t* a, uint32_t b0, uint32_t b1) {
    asm volatile("mma.sync.aligned.m16n8k16.row.col.f32.bf16.bf16.f32 "
        "{%0,%1,%2,%3},{%4,%5,%6,%7},{%8,%9},{%0,%1,%2,%3};"
        : "+f"(d[0]), "+f"(d[1]), "+f"(d[2]), "+f"(d[3])
        : "r"(a[0]), "r"(a[1]), "r"(a[2]), "r"(a[3]), "r"(b0), "r"(b1));
}
__device__ __forceinline__ uint32_t pack2(float x, float y) {
    __nv_bfloat162 t;
    t.x = __float2bfloat16_rn(x); t.y = __float2bfloat16_rn(y);
    return *(uint32_t*)&t;
}

// ---------- plumbing ----------
__global__ void k_zero(const void* adj, const void* et, const void* nt) {
    int i = blockIdx.x*blockDim.x + threadIdx.x;
    if (i < NN) { g_deg[i]=0; g_cursor[i]=0; }
    if (i < TT) { g_tcount[i]=0; g_tcur[i]=0; }
    if (i == 0) {
        g_rowptr[NN] = EE;
        int a=1,b=1,c=1;
        for (int j=0;j<128;j++) if (((const int*)adj)[2*(j*1000)+1]) { a=0; break; }
        for (int j=0;j<128;j++) if (((const int*)et )[2*(j*3000)+1]) { b=0; break; }
        for (int j=0;j<128;j++) if (((const int*)nt )[2*(j*150 )+1]) { c=0; break; }
        g_is64_adj=a; g_is64_et=b; g_is64_nt=c;
    }
}
__global__ void k_nhist(const void* nt) {
    int i = blockIdx.x*blockDim.x + threadIdx.x;
    if (i < NN) atomicAdd(&g_tcount[ld_idx(nt,i,g_is64_nt)], 1);
    __threadfence();
    __syncthreads();
    __shared__ int last;
    if (threadIdx.x == 0) last = (atomicAdd(&g_ticket1, 1) == gridDim.x - 1);
    __syncthreads();
    if (last && threadIdx.x == 0) {
        int s = 0;
        for (int t = 0; t < TT; t++) { g_tbase[t] = s; s += g_tcount[t]; }
        g_ticket1 = 0;
    }
}
__global__ void k_nscatter(const void* nt) {
    __shared__ int cnt[TT], basea[TT];
    int tid = threadIdx.x;
    if (tid < TT) cnt[tid] = 0;
    __syncthreads();
    int i = blockIdx.x*256 + tid;
    int t = -1, local = 0;
    if (i < NN) {
        t = ld_idx(nt, i, g_is64_nt);
        local = atomicAdd(&cnt[t], 1);
    }
    __syncthreads();
    if (tid < TT && cnt[tid] > 0) basea[tid] = atomicAdd(&g_tcur[tid], cnt[tid]);
    __syncthreads();
    if (t >= 0) {
        int p = g_tbase[t] + basea[t] + local;
        g_perm[p] = i;
        g_iperm[i] = p;
    }
}
__global__ void k_ehist(const void* adj) {
    int e = blockIdx.x*blockDim.x + threadIdx.x;
    if (e < EE) atomicAdd(&g_deg[g_iperm[ld_idx(adj,(long)EE+e,g_is64_adj)]], 1);
}
__global__ void k_scanA() {
    __shared__ int s[256];
    int i = blockIdx.x*256 + threadIdx.x;
    int v = (i < NN) ? g_deg[i] : 0;
    s[threadIdx.x] = v; __syncthreads();
    for (int off=1; off<256; off<<=1) {
        int t = (threadIdx.x>=off) ? s[threadIdx.x-off] : 0;
        __syncthreads(); s[threadIdx.x] += t; __syncthreads();
    }
    if (i < NN) g_rowptr[i] = s[threadIdx.x] - v;
    if (threadIdx.x == 255) g_bsum[blockIdx.x] = s[255];
    __threadfence();
    __syncthreads();
    __shared__ int last;
    if (threadIdx.x == 0) last = (atomicAdd(&g_ticket2, 1) == gridDim.x - 1);
    __syncthreads();
    if (last) {
        int j = threadIdx.x;
        int bv = (j < NB_SCAN) ? g_bsum[j] : 0;
        s[j] = bv; __syncthreads();
        for (int off=1; off<256; off<<=1) {
            int t = (j>=off) ? s[j-off] : 0;
            __syncthreads(); s[j] += t; __syncthreads();
        }
        g_boff[j] = s[j] - bv;
        if (j == 0) g_ticket2 = 0;
    }
}
__global__ void k_scanC() {
    int i = blockIdx.x*256 + threadIdx.x;
    if (i < NN) g_rowptr[i] += g_boff[blockIdx.x];
}
__global__ void k_escatter(const void* adj, const void* et) {
    int e = blockIdx.x*blockDim.x + threadIdx.x;
    if (e >= EE) return;
    int src = ld_idx(adj, e, g_is64_adj);
    int dst = ld_idx(adj, (long)EE+e, g_is64_adj);
    int r   = ld_idx(et, e, g_is64_et);
    int dp = g_iperm[dst];
    g_csr[g_rowptr[dp] + atomicAdd(&g_cursor[dp],1)] = g_iperm[src] | (r << 20);
}
// ---------- bf16 hi/lo conversions ----------
#define CVT_W0 32768
#define CVT_END (32768 + 3*TT*4096)
__global__ void k_cvtall(const float* __restrict__ att, const float* __restrict__ msg,
                         const float* __restrict__ kw, const float* __restrict__ vw,
                         const float* __restrict__ qw, const float* __restrict__ pri) {
    int i = blockIdx.x*256 + threadIdx.x;
    if (i < CVT_W0) {
        float sc = pri[i >> 12] * 0.125f;
        float a = att[i] * sc;
        __nv_bfloat16 ah = __float2bfloat16_rn(a);
        g_attH[i] = ah; g_attL[i] = __float2bfloat16_rn(a - __bfloat162float(ah));
        float m = msg[i];
        int k = i >> 6, j = i & 63;
        __nv_bfloat16 mh = __float2bfloat16_rn(m);
        g_msgTH[j*512 + k] = mh;
        g_msgTL[j*512 + k] = __float2bfloat16_rn(m - __bfloat162float(mh));
    } else if (i < CVT_END) {
        int u = i - CVT_W0;
        int rem = u & 32767;
        int e = rem & 4095;
        int k = e >> 6, c = e & 63;
        const float* W = ((u>>15) == 0) ? kw : ((u>>15) == 1) ? vw : qw;
        float v = W[rem];
        __nv_bfloat16 vh = __float2bfloat16_rn(v);
        int o = u - e + c*64 + k;
        g_wTH[o] = vh; g_wTL[o] = __float2bfloat16_rn(v - __bfloat162float(vh));
    }
}
// ---------- mma typed GEMM: knode/vnode fp32 + qn hi/lo (h converted in-kernel) ----------
__global__ __launch_bounds__(256,1) void mma_kvq(const float* __restrict__ h, const void* nt) {
    extern __shared__ __nv_bfloat16 sb[];
    __nv_bfloat16 *sAH = sb, *sAL = sb+9216;
    __nv_bfloat16 *sBH = sb+18432, *sBL = sb+18432+13824;
    int* sNode = (int*)(sb + 46080);
    int* sTy = sNode + 128;
    int tid = threadIdx.x, lane = tid & 31, w = tid >> 5;
    int base = blockIdx.x*128;
    if (tid < 128) {
        int idx = base + tid; if (idx > NN-1) idx = NN-1;
        int node = g_perm[idx];
        sNode[tid] = node;
        sTy[tid] = ld_idx(nt, node, g_is64_nt);
    }
    __syncthreads();
    for (int u = tid; u < 1024; u += 256) {
        int row = u>>3, q = u&7;
        const float4* hp = (const float4*)(h + (size_t)sNode[row]*64 + q*8);
        float4 v0 = hp[0], v1 = hp[1];
        uint32_t h0 = pack2(v0.x, v0.y), h1 = pack2(v0.z, v0.w);
        uint32_t h2 = pack2(v1.x, v1.y), h3 = pack2(v1.z, v1.w);
        __nv_bfloat162* ph;
        ph = (__nv_bfloat162*)&h0; float r0x = v0.x - __bfloat162float(ph->x), r0y = v0.y - __bfloat162float(ph->y);
        ph = (__nv_bfloat162*)&h1; float r1x = v0.z - __bfloat162float(ph->x), r1y = v0.w - __bfloat162float(ph->y);
        ph = (__nv_bfloat162*)&h2; float r2x = v1.x - __bfloat162float(ph->x), r2y = v1.y - __bfloat162float(ph->y);
        ph = (__nv_bfloat162*)&h3; float r3x = v1.z - __bfloat162float(ph->x), r3y = v1.w - __bfloat162float(ph->y);
        uint4 hv = make_uint4(h0, h1, h2, h3);
        uint4 lv = make_uint4(pack2(r0x,r0y), pack2(r1x,r1y), pack2(r2x,r2y), pack2(r3x,r3y));
        *(uint4*)(sAH + row*72 + q*8) = hv;
        *(uint4*)(sAL + row*72 + q*8) = lv;
    }
    __syncthreads();
    int m0 = w*16, r = lane>>2, cq = (lane&3)*2;
    uint32_t AH[4][4], AL[4][4];
    #pragma unroll
    for (int ks = 0; ks < 4; ks++) {
        int c = ks*16 + cq;
        AH[ks][0] = *(const uint32_t*)(sAH + (m0+r  )*72 + c);
        AH[ks][1] = *(const uint32_t*)(sAH + (m0+r+8)*72 + c);
        AH[ks][2] = *(const uint32_t*)(sAH + (m0+r  )*72 + c + 8);
        AH[ks][3] = *(const uint32_t*)(sAH + (m0+r+8)*72 + c + 8);
        AL[ks][0] = *(const uint32_t*)(sAL + (m0+r  )*72 + c);
        AL[ks][1] = *(const uint32_t*)(sAL + (m0+r+8)*72 + c);
        AL[ks][2] = *(const uint32_t*)(sAL + (m0+r  )*72 + c + 8);
        AL[ks][3] = *(const uint32_t*)(sAL + (m0+r+8)*72 + c + 8);
    }
    int t0 = sTy[0], t1 = sTy[127];
    int gr0 = base + m0 + r, gr1 = gr0 + 8;
    int row0 = m0 + r, row1 = row0 + 8;
    for (int t = t0; t <= t1; t++) {
        if (t > t0) __syncthreads();
        for (int u = tid; u < 1536; u += 256) {
            int mat = u >> 9, e = u & 511;
            int row = e>>3, q = e&7;
            size_t g = (size_t)(mat*TT + t)*4096 + row*64 + q*8;
            *(uint4*)(sBH + mat*4608 + row*72 + q*8) = *(const uint4*)(g_wTH + g);
            *(uint4*)(sBL + mat*4608 + row*72 + q*8) = *(const uint4*)(g_wTL + g);
        }
        __syncthreads();
        bool ok0 = (gr0 < NN) && (sTy[row0] == t);
        bool ok1 = (gr1 < NN) && (sTy[row1] == t);
        #pragma unroll
        for (int mat = 0; mat < 3; mat++) {
            const __nv_bfloat16 *BH = sBH + mat*4608, *BL = sBL + mat*4608;
            #pragma unroll
            for (int ntl = 0; ntl < 8; ntl++) {
                float acc[4] = {0.f,0.f,0.f,0.f};
                int brow = ntl*8 + r;
                #pragma unroll
                for (int ks = 0; ks < 4; ks++) {
                    int bc = ks*16 + cq;
                    uint32_t bh0 = *(const uint32_t*)(BH + brow*72 + bc);
                    uint32_t bh1 = *(const uint32_t*)(BH + brow*72 + bc + 8);
                    uint32_t bl0 = *(const uint32_t*)(BL + brow*72 + bc);
                    uint32_t bl1 = *(const uint32_t*)(BL + brow*72 + bc + 8);
                    mma_bf16(acc, AH[ks], bh0, bh1);
                    mma_bf16(acc, AL[ks], bh0, bh1);
                    mma_bf16(acc, AH[ks], bl0, bl1);
                }
                int gc = ntl*8 + cq;
                if (mat == 0) {
                    if (ok0) *(float2*)&g_knode[(size_t)gr0*64+gc] = make_float2(acc[0],acc[1]);
                    if (ok1) *(float2*)&g_knode[(size_t)gr1*64+gc] = make_float2(acc[2],acc[3]);
                } else if (mat == 1) {
                    if (ok0) *(float2*)&g_vnode[(size_t)gr0*64+gc] = make_float2(acc[0],acc[1]);
                    if (ok1) *(float2*)&g_vnode[(size_t)gr1*64+gc] = make_float2(acc[2],acc[3]);
                } else {
                    if (ok0) {
                        uint32_t hi = pack2(acc[0], acc[1]);
                        __nv_bfloat162* p = (__nv_bfloat162*)&hi;
                        uint32_t lo = pack2(acc[0]-__bfloat162float(p->x), acc[1]-__bfloat162float(p->y));
                        size_t o = (size_t)gr0*64+gc;
                        *(uint32_t*)&g_qnH[o]=hi; *(uint32_t*)&g_qnL[o]=lo;
                    }
                    if (ok1) {
                        uint32_t hi = pack2(acc[2], acc[3]);
                        __nv_bfloat162* p = (__nv_bfloat162*)&hi;
                        uint32_t lo = pack2(acc[2]-__bfloat162float(p->x), acc[3]-__bfloat162float(p->y));
                        size_t o = (size_t)gr1*64+gc;
                        *(uint32_t*)&g_qnH[o]=hi; *(uint32_t*)&g_qnL[o]=lo;
                    }
                }
            }
        }
    }
}
// ---------- mma GEMM 1: qrel[128,512] = qn @ att^T ----------
__global__ __launch_bounds__(256,1) void mma_qrel() {
    extern __shared__ __nv_bfloat16 sb[];
    __nv_bfloat16 *sAH = sb, *sAL = sb+9216, *sBH = sb+18432, *sBL = sb+27648;
    int tid = threadIdx.x, lane = tid & 31, w = tid >> 5;
    int base = blockIdx.x*128;
    for (int u = tid; u < 1024; u += 256) {
        int row = u>>3, q = u&7;
        int idx = base+row; if (idx > NN-1) idx = NN-1;
        *(uint4*)(sAH + row*72 + q*8) = *(const uint4*)(g_qnH + (size_t)idx*64 + q*8);
        *(uint4*)(sAL + row*72 + q*8) = *(const uint4*)(g_qnL + (size_t)idx*64 + q*8);
    }
    __syncthreads();
    int m0 = w*16, r = lane>>2, cq = (lane&3)*2;
    uint32_t AH[4][4], AL[4][4];
    #pragma unroll
    for (int ks = 0; ks < 4; ks++) {
        int c = ks*16 + cq;
        AH[ks][0] = *(const uint32_t*)(sAH + (m0+r  )*72 + c);
        AH[ks][1] = *(const uint32_t*)(sAH + (m0+r+8)*72 + c);
        AH[ks][2] = *(const uint32_t*)(sAH + (m0+r  )*72 + c + 8);
        AH[ks][3] = *(const uint32_t*)(sAH + (m0+r+8)*72 + c + 8);
        AL[ks][0] = *(const uint32_t*)(sAL + (m0+r  )*72 + c);
        AL[ks][1] = *(const uint32_t*)(sAL + (m0+r+8)*72 + c);
        AL[ks][2] = *(const uint32_t*)(sAL + (m0+r  )*72 + c + 8);
        AL[ks][3] = *(const uint32_t*)(sAL + (m0+r+8)*72 + c + 8);
    }
    int gr0 = base + m0 + r, gr1 = gr0 + 8;
    for (int nc = 0; nc < 4; nc++) {
        if (nc) __syncthreads();
        for (int u = tid; u < 1024; u += 256) {
            int row = u>>3, q = u&7;
            *(uint4*)(sBH + row*72 + q*8) = *(const uint4*)(g_attH + (size_t)(nc*128+row)*64 + q*8);
            *(uint4*)(sBL + row*72 + q*8) = *(const uint4*)(g_attL + (size_t)(nc*128+row)*64 + q*8);
        }
        __syncthreads();
        #pragma unroll 4
        for (int ntl = 0; ntl < 16; ntl++) {
            float acc[4] = {0.f, 0.f, 0.f, 0.f};
            int brow = ntl*8 + r;
            #pragma unroll
            for (int ks = 0; ks < 4; ks++) {
                int bc = ks*16 + cq;
                uint32_t bh0 = *(const uint32_t*)(sBH + brow*72 + bc);
                uint32_t bh1 = *(const uint32_t*)(sBH + brow*72 + bc + 8);
                uint32_t bl0 = *(const uint32_t*)(sBL + brow*72 + bc);
                uint32_t bl1 = *(const uint32_t*)(sBL + brow*72 + bc + 8);
                mma_bf16(acc, AH[ks], bh0, bh1);
                mma_bf16(acc, AL[ks], bh0, bh1);
                mma_bf16(acc, AH[ks], bl0, bl1);
            }
            int gc = nc*128 + ntl*8 + cq;
            if (gr0 < NN) *(float2*)&g_qrel[(size_t)gr0*512 + gc] = make_float2(acc[0], acc[1]);
            if (gr1 < NN) *(float2*)&g_qrel[(size_t)gr1*512 + gc] = make_float2(acc[2], acc[3]);
        }
    }
}
// ---------- fused edge phase: smem buckets, 8-edge MLP batching ----------
__global__ __launch_bounds__(256,1) void k_edge() {
    __shared__ float sQ[8*512];
    __shared__ float sB[8*512];
    int tid = threadIdx.x, wid = tid>>5, lane = tid & 31;
    int d = blockIdx.x*8 + wid;
    if (d >= NN) return;
    float* q = sQ + wid*512;
    float* bk = sB + wid*512;
    #pragma unroll
    for (int r = 0; r < 8; r++) {
        *(float2*)&q[r*64 + lane*2] = *(const float2*)&g_qrel[(size_t)d*512 + r*64 + lane*2];
        *(float2*)&bk[r*64 + lane*2] = make_float2(0.f, 0.f);
    }
    __syncwarp();
    int rs = g_rowptr[d], re = g_rowptr[d+1];
    float m = -3.0e38f, s = 0.f;
    for (int p = rs; p < re; p += 8) {
        int sp[8], rr[8];
        float2 vv[8];
        float sc[8];
        #pragma unroll
        for (int j = 0; j < 8; j++) {
            int pj = (p+j < re) ? p+j : re-1;
            int pk = g_csr[pj];
            sp[j] = pk & 0xFFFFF; rr[j] = pk >> 20;
        }
        #pragma unroll
        for (int j = 0; j < 8; j++) {
            float2 kv = *(const float2*)&g_knode[(size_t)sp[j]*64 + lane*2];
            float2 qs = *(const float2*)&q[rr[j]*64 + lane*2];
            sc[j] = kv.x*qs.x + kv.y*qs.y;
        }
        #pragma unroll
        for (int off = 16; off; off >>= 1) {
            #pragma unroll
            for (int j = 0; j < 8; j++)
                sc[j] += __shfl_xor_sync(~0u, sc[j], off);
        }
        #pragma unroll
        for (int j = 0; j < 8; j++) {
            vv[j] = *(const float2*)&g_vnode[(size_t)sp[j]*64 + lane*2];
            if (p+j >= re) sc[j] = -3.0e38f;
        }
        float bmax = fmaxf(fmaxf(fmaxf(sc[0], sc[1]), fmaxf(sc[2], sc[3])),
                           fmaxf(fmaxf(sc[4], sc[5]), fmaxf(sc[6], sc[7])));
        if (bmax > m) {
            float c = __expf(m - bmax);
            s *= c;
            #pragma unroll
            for (int u = 0; u < 8; u++) {
                float2 t = *(float2*)&bk[u*64 + lane*2];
                t.x *= c; t.y *= c;
                *(float2*)&bk[u*64 + lane*2] = t;
            }
            m = bmax;
        }
        float wj[8];
        #pragma unroll
        for (int j = 0; j < 8; j++) wj[j] = __expf(sc[j]-m);
        s += ((wj[0]+wj[1]) + (wj[2]+wj[3])) + ((wj[4]+wj[5]) + (wj[6]+wj[7]));
        #pragma unroll
        for (int j = 0; j < 8; j++) {
            float* ba = &bk[rr[j]*64 + lane*2];
            float2 t = *(float2*)ba;
            t.x += wj[j]*vv[j].x;
            t.y += wj[j]*vv[j].y;
            *(float2*)ba = t;
        }
    }
    float inv = 1.0f / (s + 1e-16f);
    #pragma unroll
    for (int r = 0; r < 8; r++) {
        float2 t = *(float2*)&bk[r*64 + lane*2];
        float ox = t.x*inv, oy = t.y*inv;
        __nv_bfloat162 h2, l2;
        h2.x = __float2bfloat16_rn(ox); h2.y = __float2bfloat16_rn(oy);
        l2.x = __float2bfloat16_rn(ox - __bfloat162float(h2.x));
        l2.y = __float2bfloat16_rn(oy - __bfloat162float(h2.y));
        size_t o = (size_t)d*512 + r*64 + lane*2;
        *(__nv_bfloat162*)&g_bkH[o] = h2;
        *(__nv_bfloat162*)&g_bkL[o] = l2;
    }
}
// ---------- mma GEMM 2: aggM = bucket @ msgT ----------
__global__ __launch_bounds__(256,1) void mma_agg() {
    extern __shared__ __nv_bfloat16 sb[];
    __nv_bfloat16 *sAH = sb, *sAL = sb+9216, *sBH = sb+18432, *sBL = sb+23040;
    int tid = threadIdx.x, lane = tid & 31, w = tid >> 5;
    int base = blockIdx.x*128;
    int m0 = w*16, r = lane>>2, cq = (lane&3)*2;
    float acc[8][4];
    #pragma unroll
    for (int ntl = 0; ntl < 8; ntl++)
        #pragma unroll
        for (int j = 0; j < 4; j++) acc[ntl][j] = 0.f;
    for (int kp = 0; kp < 8; kp++) {
        if (kp) __syncthreads();
        for (int u = tid; u < 1024; u += 256) {
            int row = u>>3, q = u&7;
            int idx = base+row; if (idx > NN-1) idx = NN-1;
            size_t g = (size_t)idx*512 + kp*64 + q*8;
            *(uint4*)(sAH + row*72 + q*8) = *(const uint4*)(g_bkH + g);
            *(uint4*)(sAL + row*72 + q*8) = *(const uint4*)(g_bkL + g);
        }
        for (int u = tid; u < 512; u += 256) {
            int row = u>>3, q = u&7;
            size_t g = (size_t)row*512 + kp*64 + q*8;
            *(uint4*)(sBH + row*72 + q*8) = *(const uint4*)(g_msgTH + g);
            *(uint4*)(sBL + row*72 + q*8) = *(const uint4*)(g_msgTL + g);
        }
        __syncthreads();
        uint32_t AH[4][4], AL[4][4];
        #pragma unroll
        for (int ks = 0; ks < 4; ks++) {
            int c = ks*16 + cq;
            AH[ks][0] = *(const uint32_t*)(sAH + (m0+r  )*72 + c);
            AH[ks][1] = *(const uint32_t*)(sAH + (m0+r+8)*72 + c);
            AH[ks][2] = *(const uint32_t*)(sAH + (m0+r  )*72 + c + 8);
            AH[ks][3] = *(const uint32_t*)(sAH + (m0+r+8)*72 + c + 8);
            AL[ks][0] = *(const uint32_t*)(sAL + (m0+r  )*72 + c);
            AL[ks][1] = *(const uint32_t*)(sAL + (m0+r+8)*72 + c);
            AL[ks][2] = *(const uint32_t*)(sAL + (m0+r  )*72 + c + 8);
            AL[ks][3] = *(const uint32_t*)(sAL + (m0+r+8)*72 + c + 8);
        }
        #pragma unroll
        for (int ntl = 0; ntl < 8; ntl++) {
            int brow = ntl*8 + r;
            #pragma unroll
            for (int ks = 0; ks < 4; ks++) {
                int bc = ks*16 + cq;
                uint32_t bh0 = *(const uint32_t*)(sBH + brow*72 + bc);
                uint32_t bh1 = *(const uint32_t*)(sBH + brow*72 + bc + 8);
                uint32_t bl0 = *(const uint32_t*)(sBL + brow*72 + bc);
                uint32_t bl1 = *(const uint32_t*)(sBL + brow*72 + bc + 8);
                mma_bf16(acc[ntl], AH[ks], bh0, bh1);
                mma_bf16(acc[ntl], AL[ks], bh0, bh1);
                mma_bf16(acc[ntl], AH[ks], bl0, bl1);
            }
        }
    }
    int gr0 = base + m0 + r, gr1 = gr0 + 8;
    #pragma unroll
    for (int ntl = 0; ntl < 8; ntl++) {
        int gc = ntl*8 + cq;
        if (gr0 < NN) *(float2*)&g_aggM[(size_t)gr0*64 + gc] = make_float2(acc[ntl][0], acc[ntl][1]);
        if (gr1 < NN) *(float2*)&g_aggM[(size_t)gr1*64 + gc] = make_float2(acc[ntl][2], acc[ntl][3]);
    }
}
// ---------- typed final GEMM (FFMA) ----------
__global__ __launch_bounds__(256,1) void k_outT(float* __restrict__ out, const float* __restrict__ aw,
                      const float* __restrict__ skipv, const void* nt) {
    extern __shared__ float sm[];
    float* sA = sm;
    float* sW = sA + 8192;
    int* sNode = (int*)(sW + 4096);
    int* sTy = sNode + 128;
    int tid = threadIdx.x, base = blockIdx.x*128;
    if (tid < 128) {
        int idx = base + tid; if (idx > NN-1) idx = NN-1;
        int node = g_perm[idx];
        sNode[tid] = node;
        sTy[tid] = ld_idx(nt, node, g_is64_nt);
    }
    __syncthreads();
    {
        int m = tid >> 1, half = tid & 1;
        int idx = base + m; if (idx > NN-1) idx = NN-1;
        const float4* hp = (const float4*)(g_aggM + (size_t)idx*64 + half*32);
        #pragma unroll
        for (int j = 0; j < 8; j++) {
            float4 v = hp[j]; int k0 = half*32 + j*4;
            sA[(k0+0)*128+m]=v.x; sA[(k0+1)*128+m]=v.y; sA[(k0+2)*128+m]=v.z; sA[(k0+3)*128+m]=v.w;
        }
    }
    __syncthreads();
    int t0 = sTy[0], t1 = sTy[127];
    int wy = tid >> 4, wx = tid & 15;
    int m0 = wy*8, c0 = wx*4;
    for (int t = t0; t <= t1; t++) {
        for (int e = tid; e < 1024; e += 256)
            ((float4*)sW)[e] = ((const float4*)(aw + t*4096))[e];
        __syncthreads();
        float acc[8][4];
        #pragma unroll
        for (int i = 0; i < 8; i++)
            #pragma unroll
            for (int j = 0; j < 4; j++) acc[i][j] = 0.f;
        #pragma unroll 4
        for (int k = 0; k < 64; k++) {
            float4 bw = *(const float4*)&sW[k*64+c0];
            float4 a0 = *(const float4*)&sA[k*128+m0];
            float4 a1 = *(const float4*)&sA[k*128+m0+4];
            float av[8] = {a0.x,a0.y,a0.z,a0.w,a1.x,a1.y,a1.z,a1.w};
            #pragma unroll
            for (int i = 0; i < 8; i++) {
                acc[i][0]+=av[i]*bw.x; acc[i][1]+=av[i]*bw.y; acc[i][2]+=av[i]*bw.z; acc[i][3]+=av[i]*bw.w;
            }
        }
        float sc = 1.0f / (1.0f + __expf(-skipv[t]));
        #pragma unroll
        for (int i = 0; i < 8; i++) {
            int row = m0 + i, idx = base + row;
            if (idx < NN && sTy[row] == t)
                *(float4*)&out[(size_t)sNode[row]*64+c0] =
                    make_float4(acc[i][0]*sc, acc[i][1]*sc, acc[i][2]*sc, acc[i][3]*sc);
        }
        __syncthreads();
    }
}

extern "C" void kernel_launch(void* const* d_in, const int* in_sizes, int n_in,
                              void* d_out, int out_size) {
    const float* h   = (const float*)d_in[0];
    const void*  adj = d_in[1];
    const void*  et  = d_in[2];
    const void*  nt  = d_in[3];
    int off = n_in - 8;
    const float* kw   = (const float*)d_in[off+0];
    const float* qw   = (const float*)d_in[off+1];
    const float* vw   = (const float*)d_in[off+2];
    const float* aw   = (const float*)d_in[off+3];
    const float* pri  = (const float*)d_in[off+4];
    const float* att  = (const float*)d_in[off+5];
    const float* msg  = (const float*)d_in[off+6];
    const float* skip = (const float*)d_in[off+7];
    float* out = (float*)d_out;

    static cudaStream_t s2 = nullptr, s3 = nullptr;
    static cudaEvent_t evF2 = nullptr, evF3 = nullptr, evJ2 = nullptr, evJ3 = nullptr;
    if (!s2) {
        cudaStreamCreateWithFlags(&s2, cudaStreamNonBlocking);
        cudaStreamCreateWithFlags(&s3, cudaStreamNonBlocking);
        cudaEventCreateWithFlags(&evF2, cudaEventDisableTiming);
        cudaEventCreateWithFlags(&evF3, cudaEventDisableTiming);
        cudaEventCreateWithFlags(&evJ2, cudaEventDisableTiming);
        cudaEventCreateWithFlags(&evJ3, cudaEventDisableTiming);
    }

    const int SM_KVQ  = 46080*2 + 1024 + 64;
    const int SM_QREL = 4*9216*2;
    const int SM_AGG  = (2*9216 + 2*4608)*2;
    const int SM_OUT  = (8192 + 4096)*4 + 256*4 + 16;
    cudaFuncSetAttribute(mma_kvq,  cudaFuncAttributeMaxDynamicSharedMemorySize, SM_KVQ);
    cudaFuncSetAttribute(mma_qrel, cudaFuncAttributeMaxDynamicSharedMemorySize, SM_QREL);
    cudaFuncSetAttribute(mma_agg,  cudaFuncAttributeMaxDynamicSharedMemorySize, SM_AGG);
    cudaFuncSetAttribute(k_outT,   cudaFuncAttributeMaxDynamicSharedMemorySize, SM_OUT);

    // main: zero -> nhist -> nscatter ; s3: cvtall (forked at entry, joined before mma_kvq)
    k_zero<<<(NN+255)/256,256>>>(adj, et, nt);
    cudaEventRecord(evF3, 0);
    cudaStreamWaitEvent(s3, evF3, 0);
    k_cvtall<<<(CVT_END+255)/256,256,0,s3>>>(att, msg, kw, vw, qw, pri);
    cudaEventRecord(evJ3, s3);

    k_nhist<<<(NN+255)/256,256>>>(nt);
    k_nscatter<<<(NN+255)/256,256>>>(nt);

    // fork CSR build chain onto s2 (needs iperm from nscatter)
    cudaEventRecord(evF2, 0);
    cudaStreamWaitEvent(s2, evF2, 0);
    k_ehist<<<(EE+255)/256,256,0,s2>>>(adj);
    k_scanA<<<NB_SCAN,256,0,s2>>>();
    k_scanC<<<NB_SCAN,256,0,s2>>>();
    k_escatter<<<(EE+255)/256,256,0,s2>>>(adj, et);
    cudaEventRecord(evJ2, s2);

    // main: dense chain (needs cvtall weights)
    cudaStreamWaitEvent(0, evJ3, 0);
    int nb = (NN + 127) / 128;
    mma_kvq<<<nb,256,SM_KVQ>>>(h, nt);
    mma_qrel<<<nb,256,SM_QREL>>>();

    // join CSR chain before edge phase
    cudaStreamWaitEvent(0, evJ2, 0);
    k_edge<<<(NN+7)/8,256>>>();
    mma_agg<<<nb,256,SM_AGG>>>();
    k_outT<<<nb,256,SM_OUT>>>(out, aw, skip, nt);
}

// round 17
// speedup vs baseline: 1.0123x; 1.0123x over previous
#include <cuda_runtime.h>
#include <cuda_bf16.h>
#include <stdint.h>

#define NN 50000
#define EE 800000
#define TT 8
#define NB_SCAN 196

__device__ int   g_is64_adj, g_is64_et, g_is64_nt;
__device__ int   g_ticket1, g_ticket2;
__device__ float g_knode[(size_t)NN*64];
__device__ float g_vnode[(size_t)NN*64];
__device__ __nv_bfloat16 g_qnH[(size_t)NN*64], g_qnL[(size_t)NN*64];
__device__ __nv_bfloat16 g_wTH[3*TT*4096], g_wTL[3*TT*4096];
__device__ __nv_bfloat16 g_attH[512*64], g_attL[512*64];   // pri[r]/8 folded in
__device__ __nv_bfloat16 g_msgTH[64*512], g_msgTL[64*512];
__device__ float g_qrel[(size_t)NN*512];
__device__ __nv_bfloat16 g_bkH[(size_t)NN*512], g_bkL[(size_t)NN*512];
__device__ float g_aggM[(size_t)NN*64];
__device__ int g_perm[NN], g_iperm[NN], g_deg[NN], g_cursor[NN], g_rowptr[NN+1];
__device__ int g_bsum[256], g_boff[256], g_tcount[TT], g_tbase[TT], g_tcur[TT];
__device__ int g_csr[EE];

__device__ __forceinline__ int ld_idx(const void* p, long i, int is64) {
    if (is64) return (int)(((const long long*)p)[i]);
    return ((const int*)p)[i];
}
__device__ __forceinline__ void mma_bf16(float* d, const uint32_t* a, uint32_t b0, uint32_t b1) {
    asm volatile("mma.sync.aligned.m16n8k16.row.col.f32.bf16.bf16.f32 "
        "{%0,%1,%2,%3},{%4,%5,%6,%7},{%8,%9},{%0,%1,%2,%3};"
        : "+f"(d[0]), "+f"(d[1]), "+f"(d[2]), "+f"(d[3])
        : "r"(a[0]), "r"(a[1]), "r"(a[2]), "r"(a[3]), "r"(b0), "r"(b1));
}
__device__ __forceinline__ uint32_t pack2(float x, float y) {
    __nv_bfloat162 t;
    t.x = __float2bfloat16_rn(x); t.y = __float2bfloat16_rn(y);
    return *(uint32_t*)&t;
}

// ---------- plumbing ----------
__global__ void k_zero(const void* adj, const void* et, const void* nt) {
    int i = blockIdx.x*blockDim.x + threadIdx.x;
    if (i < NN) { g_deg[i]=0; g_cursor[i]=0; }
    if (i < TT) { g_tcount[i]=0; g_tcur[i]=0; }
    if (i == 0) {
        g_rowptr[NN] = EE;
        int a=1,b=1,c=1;
        for (int j=0;j<128;j++) if (((const int*)adj)[2*(j*1000)+1]) { a=0; break; }
        for (int j=0;j<128;j++) if (((const int*)et )[2*(j*3000)+1]) { b=0; break; }
        for (int j=0;j<128;j++) if (((const int*)nt )[2*(j*150 )+1]) { c=0; break; }
        g_is64_adj=a; g_is64_et=b; g_is64_nt=c;
    }
}
__global__ void k_nhist(const void* nt) {
    int i = blockIdx.x*blockDim.x + threadIdx.x;
    if (i < NN) atomicAdd(&g_tcount[ld_idx(nt,i,g_is64_nt)], 1);
    __threadfence();
    __syncthreads();
    __shared__ int last;
    if (threadIdx.x == 0) last = (atomicAdd(&g_ticket1, 1) == gridDim.x - 1);
    __syncthreads();
    if (last && threadIdx.x == 0) {
        int s = 0;
        for (int t = 0; t < TT; t++) { g_tbase[t] = s; s += g_tcount[t]; }
        g_ticket1 = 0;
    }
}
__global__ void k_nscatter(const void* nt) {
    __shared__ int cnt[TT], basea[TT];
    int tid = threadIdx.x;
    if (tid < TT) cnt[tid] = 0;
    __syncthreads();
    int i = blockIdx.x*256 + tid;
    int t = -1, local = 0;
    if (i < NN) {
        t = ld_idx(nt, i, g_is64_nt);
        local = atomicAdd(&cnt[t], 1);
    }
    __syncthreads();
    if (tid < TT && cnt[tid] > 0) basea[tid] = atomicAdd(&g_tcur[tid], cnt[tid]);
    __syncthreads();
    if (t >= 0) {
        int p = g_tbase[t] + basea[t] + local;
        g_perm[p] = i;
        g_iperm[i] = p;
    }
}
__global__ void k_ehist(const void* adj) {
    int e = blockIdx.x*blockDim.x + threadIdx.x;
    if (e < EE) atomicAdd(&g_deg[g_iperm[ld_idx(adj,(long)EE+e,g_is64_adj)]], 1);
}
__global__ void k_scanA() {
    __shared__ int s[256];
    int i = blockIdx.x*256 + threadIdx.x;
    int v = (i < NN) ? g_deg[i] : 0;
    s[threadIdx.x] = v; __syncthreads();
    for (int off=1; off<256; off<<=1) {
        int t = (threadIdx.x>=off) ? s[threadIdx.x-off] : 0;
        __syncthreads(); s[threadIdx.x] += t; __syncthreads();
    }
    if (i < NN) g_rowptr[i] = s[threadIdx.x] - v;
    if (threadIdx.x == 255) g_bsum[blockIdx.x] = s[255];
    __threadfence();
    __syncthreads();
    __shared__ int last;
    if (threadIdx.x == 0) last = (atomicAdd(&g_ticket2, 1) == gridDim.x - 1);
    __syncthreads();
    if (last) {
        int j = threadIdx.x;
        int bv = (j < NB_SCAN) ? g_bsum[j] : 0;
        s[j] = bv; __syncthreads();
        for (int off=1; off<256; off<<=1) {
            int t = (j>=off) ? s[j-off] : 0;
            __syncthreads(); s[j] += t; __syncthreads();
        }
        g_boff[j] = s[j] - bv;
        if (j == 0) g_ticket2 = 0;
    }
}
__global__ void k_scanC() {
    int i = blockIdx.x*256 + threadIdx.x;
    if (i < NN) g_rowptr[i] += g_boff[blockIdx.x];
}
__global__ void k_escatter(const void* adj, const void* et) {
    int e = blockIdx.x*blockDim.x + threadIdx.x;
    if (e >= EE) return;
    int src = ld_idx(adj, e, g_is64_adj);
    int dst = ld_idx(adj, (long)EE+e, g_is64_adj);
    int r   = ld_idx(et, e, g_is64_et);
    int dp = g_iperm[dst];
    g_csr[g_rowptr[dp] + atomicAdd(&g_cursor[dp],1)] = g_iperm[src] | (r << 20);
}
// ---------- bf16 hi/lo conversions ----------
#define CVT_W0 32768
#define CVT_END (32768 + 3*TT*4096)
__global__ void k_cvtall(const float* __restrict__ att, const float* __restrict__ msg,
                         const float* __restrict__ kw, const float* __restrict__ vw,
                         const float* __restrict__ qw, const float* __restrict__ pri) {
    int i = blockIdx.x*256 + threadIdx.x;
    if (i < CVT_W0) {
        float sc = pri[i >> 12] * 0.125f;
        float a = att[i] * sc;
        __nv_bfloat16 ah = __float2bfloat16_rn(a);
        g_attH[i] = ah; g_attL[i] = __float2bfloat16_rn(a - __bfloat162float(ah));
        float m = msg[i];
        int k = i >> 6, j = i & 63;
        __nv_bfloat16 mh = __float2bfloat16_rn(m);
        g_msgTH[j*512 + k] = mh;
        g_msgTL[j*512 + k] = __float2bfloat16_rn(m - __bfloat162float(mh));
    } else if (i < CVT_END) {
        int u = i - CVT_W0;
        int rem = u & 32767;
        int e = rem & 4095;
        int k = e >> 6, c = e & 63;
        const float* W = ((u>>15) == 0) ? kw : ((u>>15) == 1) ? vw : qw;
        float v = W[rem];
        __nv_bfloat16 vh = __float2bfloat16_rn(v);
        int o = u - e + c*64 + k;
        g_wTH[o] = vh; g_wTL[o] = __float2bfloat16_rn(v - __bfloat162float(vh));
    }
}
// ---------- mma typed GEMM: knode/vnode fp32 + qn hi/lo (h converted in-kernel) ----------
__global__ __launch_bounds__(256,1) void mma_kvq(const float* __restrict__ h, const void* nt) {
    extern __shared__ __nv_bfloat16 sb[];
    __nv_bfloat16 *sAH = sb, *sAL = sb+9216;
    __nv_bfloat16 *sBH = sb+18432, *sBL = sb+18432+13824;
    int* sNode = (int*)(sb + 46080);
    int* sTy = sNode + 128;
    int tid = threadIdx.x, lane = tid & 31, w = tid >> 5;
    int base = blockIdx.x*128;
    if (tid < 128) {
        int idx = base + tid; if (idx > NN-1) idx = NN-1;
        int node = g_perm[idx];
        sNode[tid] = node;
        sTy[tid] = ld_idx(nt, node, g_is64_nt);
    }
    __syncthreads();
    for (int u = tid; u < 1024; u += 256) {
        int row = u>>3, q = u&7;
        const float4* hp = (const float4*)(h + (size_t)sNode[row]*64 + q*8);
        float4 v0 = hp[0], v1 = hp[1];
        uint32_t h0 = pack2(v0.x, v0.y), h1 = pack2(v0.z, v0.w);
        uint32_t h2 = pack2(v1.x, v1.y), h3 = pack2(v1.z, v1.w);
        __nv_bfloat162* ph;
        ph = (__nv_bfloat162*)&h0; float r0x = v0.x - __bfloat162float(ph->x), r0y = v0.y - __bfloat162float(ph->y);
        ph = (__nv_bfloat162*)&h1; float r1x = v0.z - __bfloat162float(ph->x), r1y = v0.w - __bfloat162float(ph->y);
        ph = (__nv_bfloat162*)&h2; float r2x = v1.x - __bfloat162float(ph->x), r2y = v1.y - __bfloat162float(ph->y);
        ph = (__nv_bfloat162*)&h3; float r3x = v1.z - __bfloat162float(ph->x), r3y = v1.w - __bfloat162float(ph->y);
        uint4 hv = make_uint4(h0, h1, h2, h3);
        uint4 lv = make_uint4(pack2(r0x,r0y), pack2(r1x,r1y), pack2(r2x,r2y), pack2(r3x,r3y));
        *(uint4*)(sAH + row*72 + q*8) = hv;
        *(uint4*)(sAL + row*72 + q*8) = lv;
    }
    __syncthreads();
    int m0 = w*16, r = lane>>2, cq = (lane&3)*2;
    uint32_t AH[4][4], AL[4][4];
    #pragma unroll
    for (int ks = 0; ks < 4; ks++) {
        int c = ks*16 + cq;
        AH[ks][0] = *(const uint32_t*)(sAH + (m0+r  )*72 + c);
        AH[ks][1] = *(const uint32_t*)(sAH + (m0+r+8)*72 + c);
        AH[ks][2] = *(const uint32_t*)(sAH + (m0+r  )*72 + c + 8);
        AH[ks][3] = *(const uint32_t*)(sAH + (m0+r+8)*72 + c + 8);
        AL[ks][0] = *(const uint32_t*)(sAL + (m0+r  )*72 + c);
        AL[ks][1] = *(const uint32_t*)(sAL + (m0+r+8)*72 + c);
        AL[ks][2] = *(const uint32_t*)(sAL + (m0+r  )*72 + c + 8);
        AL[ks][3] = *(const uint32_t*)(sAL + (m0+r+8)*72 + c + 8);
    }
    int t0 = sTy[0], t1 = sTy[127];
    int gr0 = base + m0 + r, gr1 = gr0 + 8;
    int row0 = m0 + r, row1 = row0 + 8;
    for (int t = t0; t <= t1; t++) {
        if (t > t0) __syncthreads();
        for (int u = tid; u < 1536; u += 256) {
            int mat = u >> 9, e = u & 511;
            int row = e>>3, q = e&7;
            size_t g = (size_t)(mat*TT + t)*4096 + row*64 + q*8;
            *(uint4*)(sBH + mat*4608 + row*72 + q*8) = *(const uint4*)(g_wTH + g);
            *(uint4*)(sBL + mat*4608 + row*72 + q*8) = *(const uint4*)(g_wTL + g);
        }
        __syncthreads();
        bool ok0 = (gr0 < NN) && (sTy[row0] == t);
        bool ok1 = (gr1 < NN) && (sTy[row1] == t);
        #pragma unroll
        for (int mat = 0; mat < 3; mat++) {
            const __nv_bfloat16 *BH = sBH + mat*4608, *BL = sBL + mat*4608;
            #pragma unroll
            for (int ntl = 0; ntl < 8; ntl++) {
                float acc[4] = {0.f,0.f,0.f,0.f};
                int brow = ntl*8 + r;
                #pragma unroll
                for (int ks = 0; ks < 4; ks++) {
                    int bc = ks*16 + cq;
                    uint32_t bh0 = *(const uint32_t*)(BH + brow*72 + bc);
                    uint32_t bh1 = *(const uint32_t*)(BH + brow*72 + bc + 8);
                    uint32_t bl0 = *(const uint32_t*)(BL + brow*72 + bc);
                    uint32_t bl1 = *(const uint32_t*)(BL + brow*72 + bc + 8);
                    mma_bf16(acc, AH[ks], bh0, bh1);
                    mma_bf16(acc, AL[ks], bh0, bh1);
                    mma_bf16(acc, AH[ks], bl0, bl1);
                }
                int gc = ntl*8 + cq;
                if (mat == 0) {
                    if (ok0) *(float2*)&g_knode[(size_t)gr0*64+gc] = make_float2(acc[0],acc[1]);
                    if (ok1) *(float2*)&g_knode[(size_t)gr1*64+gc] = make_float2(acc[2],acc[3]);
                } else if (mat == 1) {
                    if (ok0) *(float2*)&g_vnode[(size_t)gr0*64+gc] = make_float2(acc[0],acc[1]);
                    if (ok1) *(float2*)&g_vnode[(size_t)gr1*64+gc] = make_float2(acc[2],acc[3]);
                } else {
                    if (ok0) {
                        uint32_t hi = pack2(acc[0], acc[1]);
                        __nv_bfloat162* p = (__nv_bfloat162*)&hi;
                        uint32_t lo = pack2(acc[0]-__bfloat162float(p->x), acc[1]-__bfloat162float(p->y));
                        size_t o = (size_t)gr0*64+gc;
                        *(uint32_t*)&g_qnH[o]=hi; *(uint32_t*)&g_qnL[o]=lo;
                    }
                    if (ok1) {
                        uint32_t hi = pack2(acc[2], acc[3]);
                        __nv_bfloat162* p = (__nv_bfloat162*)&hi;
                        uint32_t lo = pack2(acc[2]-__bfloat162float(p->x), acc[3]-__bfloat162float(p->y));
                        size_t o = (size_t)gr1*64+gc;
                        *(uint32_t*)&g_qnH[o]=hi; *(uint32_t*)&g_qnL[o]=lo;
                    }
                }
            }
        }
    }
}
// ---------- mma GEMM 1: qrel[128,512] = qn @ att^T ----------
__global__ __launch_bounds__(256,1) void mma_qrel() {
    extern __shared__ __nv_bfloat16 sb[];
    __nv_bfloat16 *sAH = sb, *sAL = sb+9216, *sBH = sb+18432, *sBL = sb+27648;
    int tid = threadIdx.x, lane = tid & 31, w = tid >> 5;
    int base = blockIdx.x*128;
    for (int u = tid; u < 1024; u += 256) {
        int row = u>>3, q = u&7;
        int idx = base+row; if (idx > NN-1) idx = NN-1;
        *(uint4*)(sAH + row*72 + q*8) = *(const uint4*)(g_qnH + (size_t)idx*64 + q*8);
        *(uint4*)(sAL + row*72 + q*8) = *(const uint4*)(g_qnL + (size_t)idx*64 + q*8);
    }
    __syncthreads();
    int m0 = w*16, r = lane>>2, cq = (lane&3)*2;
    uint32_t AH[4][4], AL[4][4];
    #pragma unroll
    for (int ks = 0; ks < 4; ks++) {
        int c = ks*16 + cq;
        AH[ks][0] = *(const uint32_t*)(sAH + (m0+r  )*72 + c);
        AH[ks][1] = *(const uint32_t*)(sAH + (m0+r+8)*72 + c);
        AH[ks][2] = *(const uint32_t*)(sAH + (m0+r  )*72 + c + 8);
        AH[ks][3] = *(const uint32_t*)(sAH + (m0+r+8)*72 + c + 8);
        AL[ks][0] = *(const uint32_t*)(sAL + (m0+r  )*72 + c);
        AL[ks][1] = *(const uint32_t*)(sAL + (m0+r+8)*72 + c);
        AL[ks][2] = *(const uint32_t*)(sAL + (m0+r  )*72 + c + 8);
        AL[ks][3] = *(const uint32_t*)(sAL + (m0+r+8)*72 + c + 8);
    }
    int gr0 = base + m0 + r, gr1 = gr0 + 8;
    for (int nc = 0; nc < 4; nc++) {
        if (nc) __syncthreads();
        for (int u = tid; u < 1024; u += 256) {
            int row = u>>3, q = u&7;
            *(uint4*)(sBH + row*72 + q*8) = *(const uint4*)(g_attH + (size_t)(nc*128+row)*64 + q*8);
            *(uint4*)(sBL + row*72 + q*8) = *(const uint4*)(g_attL + (size_t)(nc*128+row)*64 + q*8);
        }
        __syncthreads();
        #pragma unroll 4
        for (int ntl = 0; ntl < 16; ntl++) {
            float acc[4] = {0.f, 0.f, 0.f, 0.f};
            int brow = ntl*8 + r;
            #pragma unroll
            for (int ks = 0; ks < 4; ks++) {
                int bc = ks*16 + cq;
                uint32_t bh0 = *(const uint32_t*)(sBH + brow*72 + bc);
                uint32_t bh1 = *(const uint32_t*)(sBH + brow*72 + bc + 8);
                uint32_t bl0 = *(const uint32_t*)(sBL + brow*72 + bc);
                uint32_t bl1 = *(const uint32_t*)(sBL + brow*72 + bc + 8);
                mma_bf16(acc, AH[ks], bh0, bh1);
                mma_bf16(acc, AL[ks], bh0, bh1);
                mma_bf16(acc, AH[ks], bl0, bl1);
            }
            int gc = nc*128 + ntl*8 + cq;
            if (gr0 < NN) *(float2*)&g_qrel[(size_t)gr0*512 + gc] = make_float2(acc[0], acc[1]);
            if (gr1 < NN) *(float2*)&g_qrel[(size_t)gr1*512 + gc] = make_float2(acc[2], acc[3]);
        }
    }
}
// ---------- fused edge phase: deferred batch-max online softmax ----------
__global__ __launch_bounds__(256,1) void k_edge() {
    __shared__ float sQ[8*512];
    int tid = threadIdx.x, wid = tid>>5, lane = tid & 31;
    int d = blockIdx.x*8 + wid;
    if (d >= NN) return;
    float* q = sQ + wid*512;
    #pragma unroll
    for (int r = 0; r < 8; r++)
        *(float2*)&q[r*64 + lane*2] = *(const float2*)&g_qrel[(size_t)d*512 + r*64 + lane*2];
    __syncwarp();
    int rs = g_rowptr[d], re = g_rowptr[d+1];
    float m = -3.0e38f, s = 0.f;
    float2 b[8];
    #pragma unroll
    for (int r = 0; r < 8; r++) b[r] = make_float2(0.f,0.f);
    for (int p = rs; p < re; p += 4) {
        int sp[4], rr[4];
        float2 vv[4];
        float sc[4];
        #pragma unroll
        for (int j = 0; j < 4; j++) {
            int pj = (p+j < re) ? p+j : re-1;
            int pk = g_csr[pj];
            sp[j] = pk & 0xFFFFF; rr[j] = pk >> 20;
            float2 kv = *(const float2*)&g_knode[(size_t)sp[j]*64 + lane*2];
            float2 qs = *(const float2*)&q[rr[j]*64 + lane*2];
            sc[j] = kv.x*qs.x + kv.y*qs.y;
        }
        #pragma unroll
        for (int off = 16; off; off >>= 1) {
            sc[0] += __shfl_xor_sync(~0u, sc[0], off);
            sc[1] += __shfl_xor_sync(~0u, sc[1], off);
            sc[2] += __shfl_xor_sync(~0u, sc[2], off);
            sc[3] += __shfl_xor_sync(~0u, sc[3], off);
        }
        #pragma unroll
        for (int j = 0; j < 4; j++) {
            vv[j] = *(const float2*)&g_vnode[(size_t)sp[j]*64 + lane*2];
            if (p+j >= re) sc[j] = -3.0e38f;
        }
        float bmax = fmaxf(fmaxf(sc[0], sc[1]), fmaxf(sc[2], sc[3]));
        if (bmax > m) {
            float c = __expf(m - bmax);
            s *= c;
            #pragma unroll
            for (int u = 0; u < 8; u++) { b[u].x *= c; b[u].y *= c; }
            m = bmax;
        }
        float w0 = __expf(sc[0]-m), w1 = __expf(sc[1]-m);
        float w2 = __expf(sc[2]-m), w3 = __expf(sc[3]-m);
        s += (w0+w1) + (w2+w3);
        float wj[4] = {w0, w1, w2, w3};
        #pragma unroll
        for (int j = 0; j < 4; j++) {
            int rj = rr[j];
            #pragma unroll
            for (int u = 0; u < 8; u++)
                if (rj == u) { b[u].x += wj[j]*vv[j].x; b[u].y += wj[j]*vv[j].y; }
        }
    }
    float inv = 1.0f / (s + 1e-16f);
    #pragma unroll
    for (int r = 0; r < 8; r++) {
        float ox = b[r].x*inv, oy = b[r].y*inv;
        __nv_bfloat162 h2, l2;
        h2.x = __float2bfloat16_rn(ox); h2.y = __float2bfloat16_rn(oy);
        l2.x = __float2bfloat16_rn(ox - __bfloat162float(h2.x));
        l2.y = __float2bfloat16_rn(oy - __bfloat162float(h2.y));
        size_t o = (size_t)d*512 + r*64 + lane*2;
        *(__nv_bfloat162*)&g_bkH[o] = h2;
        *(__nv_bfloat162*)&g_bkL[o] = l2;
    }
}
// ---------- mma GEMM 2: aggM = bucket @ msgT ----------
__global__ __launch_bounds__(256,1) void mma_agg() {
    extern __shared__ __nv_bfloat16 sb[];
    __nv_bfloat16 *sAH = sb, *sAL = sb+9216, *sBH = sb+18432, *sBL = sb+23040;
    int tid = threadIdx.x, lane = tid & 31, w = tid >> 5;
    int base = blockIdx.x*128;
    int m0 = w*16, r = lane>>2, cq = (lane&3)*2;
    float acc[8][4];
    #pragma unroll
    for (int ntl = 0; ntl < 8; ntl++)
        #pragma unroll
        for (int j = 0; j < 4; j++) acc[ntl][j] = 0.f;
    for (int kp = 0; kp < 8; kp++) {
        if (kp) __syncthreads();
        for (int u = tid; u < 1024; u += 256) {
            int row = u>>3, q = u&7;
            int idx = base+row; if (idx > NN-1) idx = NN-1;
            size_t g = (size_t)idx*512 + kp*64 + q*8;
            *(uint4*)(sAH + row*72 + q*8) = *(const uint4*)(g_bkH + g);
            *(uint4*)(sAL + row*72 + q*8) = *(const uint4*)(g_bkL + g);
        }
        for (int u = tid; u < 512; u += 256) {
            int row = u>>3, q = u&7;
            size_t g = (size_t)row*512 + kp*64 + q*8;
            *(uint4*)(sBH + row*72 + q*8) = *(const uint4*)(g_msgTH + g);
            *(uint4*)(sBL + row*72 + q*8) = *(const uint4*)(g_msgTL + g);
        }
        __syncthreads();
        uint32_t AH[4][4], AL[4][4];
        #pragma unroll
        for (int ks = 0; ks < 4; ks++) {
            int c = ks*16 + cq;
            AH[ks][0] = *(const uint32_t*)(sAH + (m0+r  )*72 + c);
            AH[ks][1] = *(const uint32_t*)(sAH + (m0+r+8)*72 + c);
            AH[ks][2] = *(const uint32_t*)(sAH + (m0+r  )*72 + c + 8);
            AH[ks][3] = *(const uint32_t*)(sAH + (m0+r+8)*72 + c + 8);
            AL[ks][0] = *(const uint32_t*)(sAL + (m0+r  )*72 + c);
            AL[ks][1] = *(const uint32_t*)(sAL + (m0+r+8)*72 + c);
            AL[ks][2] = *(const uint32_t*)(sAL + (m0+r  )*72 + c + 8);
            AL[ks][3] = *(const uint32_t*)(sAL + (m0+r+8)*72 + c + 8);
        }
        #pragma unroll
        for (int ntl = 0; ntl < 8; ntl++) {
            int brow = ntl*8 + r;
            #pragma unroll
            for (int ks = 0; ks < 4; ks++) {
                int bc = ks*16 + cq;
                uint32_t bh0 = *(const uint32_t*)(sBH + brow*72 + bc);
                uint32_t bh1 = *(const uint32_t*)(sBH + brow*72 + bc + 8);
                uint32_t bl0 = *(const uint32_t*)(sBL + brow*72 + bc);
                uint32_t bl1 = *(const uint32_t*)(sBL + brow*72 + bc + 8);
                mma_bf16(acc[ntl], AH[ks], bh0, bh1);
                mma_bf16(acc[ntl], AL[ks], bh0, bh1);
                mma_bf16(acc[ntl], AH[ks], bl0, bl1);
            }
        }
    }
    int gr0 = base + m0 + r, gr1 = gr0 + 8;
    #pragma unroll
    for (int ntl = 0; ntl < 8; ntl++) {
        int gc = ntl*8 + cq;
        if (gr0 < NN) *(float2*)&g_aggM[(size_t)gr0*64 + gc] = make_float2(acc[ntl][0], acc[ntl][1]);
        if (gr1 < NN) *(float2*)&g_aggM[(size_t)gr1*64 + gc] = make_float2(acc[ntl][2], acc[ntl][3]);
    }
}
// ---------- typed final GEMM (FFMA) ----------
__global__ __launch_bounds__(256,1) void k_outT(float* __restrict__ out, const float* __restrict__ aw,
                      const float* __restrict__ skipv, const void* nt) {
    extern __shared__ float sm[];
    float* sA = sm;
    float* sW = sA + 8192;
    int* sNode = (int*)(sW + 4096);
    int* sTy = sNode + 128;
    int tid = threadIdx.x, base = blockIdx.x*128;
    if (tid < 128) {
        int idx = base + tid; if (idx > NN-1) idx = NN-1;
        int node = g_perm[idx];
        sNode[tid] = node;
        sTy[tid] = ld_idx(nt, node, g_is64_nt);
    }
    __syncthreads();
    {
        int m = tid >> 1, half = tid & 1;
        int idx = base + m; if (idx > NN-1) idx = NN-1;
        const float4* hp = (const float4*)(g_aggM + (size_t)idx*64 + half*32);
        #pragma unroll
        for (int j = 0; j < 8; j++) {
            float4 v = hp[j]; int k0 = half*32 + j*4;
            sA[(k0+0)*128+m]=v.x; sA[(k0+1)*128+m]=v.y; sA[(k0+2)*128+m]=v.z; sA[(k0+3)*128+m]=v.w;
        }
    }
    __syncthreads();
    int t0 = sTy[0], t1 = sTy[127];
    int wy = tid >> 4, wx = tid & 15;
    int m0 = wy*8, c0 = wx*4;
    for (int t = t0; t <= t1; t++) {
        for (int e = tid; e < 1024; e += 256)
            ((float4*)sW)[e] = ((const float4*)(aw + t*4096))[e];
        __syncthreads();
        float acc[8][4];
        #pragma unroll
        for (int i = 0; i < 8; i++)
            #pragma unroll
            for (int j = 0; j < 4; j++) acc[i][j] = 0.f;
        #pragma unroll 4
        for (int k = 0; k < 64; k++) {
            float4 bw = *(const float4*)&sW[k*64+c0];
            float4 a0 = *(const float4*)&sA[k*128+m0];
            float4 a1 = *(const float4*)&sA[k*128+m0+4];
            float av[8] = {a0.x,a0.y,a0.z,a0.w,a1.x,a1.y,a1.z,a1.w};
            #pragma unroll
            for (int i = 0; i < 8; i++) {
                acc[i][0]+=av[i]*bw.x; acc[i][1]+=av[i]*bw.y; acc[i][2]+=av[i]*bw.z; acc[i][3]+=av[i]*bw.w;
            }
        }
        float sc = 1.0f / (1.0f + __expf(-skipv[t]));
        #pragma unroll
        for (int i = 0; i < 8; i++) {
            int row = m0 + i, idx = base + row;
            if (idx < NN && sTy[row] == t)
                *(float4*)&out[(size_t)sNode[row]*64+c0] =
                    make_float4(acc[i][0]*sc, acc[i][1]*sc, acc[i][2]*sc, acc[i][3]*sc);
        }
        __syncthreads();
    }
}

extern "C" void kernel_launch(void* const* d_in, const int* in_sizes, int n_in,
                              void* d_out, int out_size) {
    const float* h   = (const float*)d_in[0];
    const void*  adj = d_in[1];
    const void*  et  = d_in[2];
    const void*  nt  = d_in[3];
    int off = n_in - 8;
    const float* kw   = (const float*)d_in[off+0];
    const float* qw   = (const float*)d_in[off+1];
    const float* vw   = (const float*)d_in[off+2];
    const float* aw   = (const float*)d_in[off+3];
    const float* pri  = (const float*)d_in[off+4];
    const float* att  = (const float*)d_in[off+5];
    const float* msg  = (const float*)d_in[off+6];
    const float* skip = (const float*)d_in[off+7];
    float* out = (float*)d_out;

    static cudaStream_t s2 = nullptr, s3 = nullptr;
    static cudaEvent_t evF2 = nullptr, evF3 = nullptr, evJ2 = nullptr, evJ3 = nullptr;
    if (!s2) {
        cudaStreamCreateWithFlags(&s2, cudaStreamNonBlocking);
        cudaStreamCreateWithFlags(&s3, cudaStreamNonBlocking);
        cudaEventCreateWithFlags(&evF2, cudaEventDisableTiming);
        cudaEventCreateWithFlags(&evF3, cudaEventDisableTiming);
        cudaEventCreateWithFlags(&evJ2, cudaEventDisableTiming);
        cudaEventCreateWithFlags(&evJ3, cudaEventDisableTiming);
    }

    const int SM_KVQ  = 46080*2 + 1024 + 64;
    const int SM_QREL = 4*9216*2;
    const int SM_AGG  = (2*9216 + 2*4608)*2;
    const int SM_OUT  = (8192 + 4096)*4 + 256*4 + 16;
    cudaFuncSetAttribute(mma_kvq,  cudaFuncAttributeMaxDynamicSharedMemorySize, SM_KVQ);
    cudaFuncSetAttribute(mma_qrel, cudaFuncAttributeMaxDynamicSharedMemorySize, SM_QREL);
    cudaFuncSetAttribute(mma_agg,  cudaFuncAttributeMaxDynamicSharedMemorySize, SM_AGG);
    cudaFuncSetAttribute(k_outT,   cudaFuncAttributeMaxDynamicSharedMemorySize, SM_OUT);

    // main: zero -> nhist -> nscatter ; s3: cvtall (forked at entry, joined before mma_kvq)
    k_zero<<<(NN+255)/256,256>>>(adj, et, nt);
    cudaEventRecord(evF3, 0);
    cudaStreamWaitEvent(s3, evF3, 0);
    k_cvtall<<<(CVT_END+255)/256,256,0,s3>>>(att, msg, kw, vw, qw, pri);
    cudaEventRecord(evJ3, s3);

    k_nhist<<<(NN+255)/256,256>>>(nt);
    k_nscatter<<<(NN+255)/256,256>>>(nt);

    // fork CSR build chain onto s2 (needs iperm from nscatter)
    cudaEventRecord(evF2, 0);
    cudaStreamWaitEvent(s2, evF2, 0);
    k_ehist<<<(EE+255)/256,256,0,s2>>>(adj);
    k_scanA<<<NB_SCAN,256,0,s2>>>();
    k_scanC<<<NB_SCAN,256,0,s2>>>();
    k_escatter<<<(EE+255)/256,256,0,s2>>>(adj, et);
    cudaEventRecord(evJ2, s2);

    // main: dense chain (needs cvtall weights)
    cudaStreamWaitEvent(0, evJ3, 0);
    int nb = (NN + 127) / 128;
    mma_kvq<<<nb,256,SM_KVQ>>>(h, nt);
    mma_qrel<<<nb,256,SM_QREL>>>();

    // join CSR chain before edge phase
    cudaStreamWaitEvent(0, evJ2, 0);
    k_edge<<<(NN+7)/8,256>>>();
    mma_agg<<<nb,256,SM_AGG>>>();
    k_outT<<<nb,256,SM_OUT>>>(out, aw, skip, nt);
}